// round 11
// baseline (speedup 1.0000x reference)
#include <cuda_runtime.h>
#include <math.h>

constexpr int T = 512, B = 32, DIN = 41, H = 800;
constexpr int UPB = 12;                 // units per block
constexpr int BPD = 67;                 // blocks per direction (66 full + 1x8)
constexpr int NBLK = 2 * BPD;           // 134 persistent blocks
constexpr int SHF = 804;                // smem h row stride in floats (201 x 16B)
constexpr int SXS = 52;                 // padded input K (13 x 16B, odd units)
typedef unsigned long long ull;

// ---------------- scratch ----------------
__device__ float g_hstate[2][2][B][H];  // [phase][dir][b][k]
__device__ float g_h1[T][B][2 * H];
__device__ float g_h2[T][B][2 * H];
__device__ float g_xs1[2][T][4 * H][B];
__device__ float g_Wp[2][4 * H][SXS];   // zero-padded Wih layer0
__device__ float g_ang[T][B][3];
__device__ int   g_bar[2][T];

// ---------------- helpers ----------------
__device__ __forceinline__ void ffma2(ull& d, ull a, ull b) {
    asm("fma.rn.f32x2 %0, %1, %2, %0;" : "+l"(d) : "l"(a), "l"(b));
}
__device__ __forceinline__ float hadd(ull v) {
    float lo, hi;
    asm("mov.b64 {%0,%1}, %2;" : "=f"(lo), "=f"(hi) : "l"(v));
    return lo + hi;
}
__device__ __forceinline__ float sigm(float x) { return 1.0f / (1.0f + expf(-x)); }

// ---------------- init ----------------
__global__ void zero_kernel(int zero_bar) {
    int i = blockIdx.x * blockDim.x + threadIdx.x;
    if (i < 2 * 2 * B * H) ((float*)g_hstate)[i] = 0.0f;
    if (zero_bar && i < 2 * T) ((int*)g_bar)[i] = 0;
}

__global__ void prep_wp(const float* __restrict__ Wf, const float* __restrict__ Wb) {
    int i = blockIdx.x * blockDim.x + threadIdx.x;
    if (i >= 2 * 4 * H * SXS) return;
    int dir = i / (4 * H * SXS);
    int rem = i % (4 * H * SXS);
    int r = rem / SXS, k = rem % SXS;
    const float* W = dir ? Wb : Wf;
    ((float*)g_Wp)[i] = (k < DIN) ? W[r * DIN + k] : 0.0f;
}

// ---------------- persistent bi-LSTM layer (batch-major warps) ----------------
// 134 blocks x 384 threads = 12 warps. Warp w -> (rg = w%6, ks = w/6).
// Warp owns 8 gate-rows (r = rg*8+j), k-slice ks*400, ALL 32 batches (lane=b).
// Weight loads are warp-uniform (1 wavefront); h via LDS.128 stride-201 units.
// Update role: thread (u = warp id < 12, b = lane); c in a register.
template <int LAYER>
__global__ void __launch_bounds__(384, 1) lstm_persist(
    const float* __restrict__ x,
    const float* __restrict__ Whh_f, const float* __restrict__ b_f,
    const float* __restrict__ Whh_b, const float* __restrict__ b_b)
{
    extern __shared__ float smem[];
    float* sh = smem;                        // [32][804]
    float* sx = smem + 32 * SHF;             // [32][52]
    ull*  sredU = (ull*)(smem + 32 * SHF + 32 * SXS);  // [2ks][48r][32b]

    const int tid  = threadIdx.x;
    const int w    = tid >> 5;               // warp 0..11
    const int lane = tid & 31;               // batch
    const int rg   = w % 6, ks = w / 6;

    const int blk  = blockIdx.x;
    const int dir  = (blk >= BPD);
    const int ublk = dir ? blk - BPD : blk;
    const int UB    = (800 - ublk * UPB < UPB) ? (800 - ublk * UPB) : UPB;
    const int ubase = ublk * UPB;

    const float* __restrict__ Whh = dir ? Whh_b : Whh_f;
    const float* __restrict__ bia = dir ? b_b : b_f;

    // 8 weight-row pointers (warp-uniform addresses)
    const float* wrow[8];
    int rowg[8];
#pragma unroll
    for (int j = 0; j < 8; j++) {
        int r = rg * 8 + j;
        int g = r / 12, ur = r % 12;
        if (ur >= UB) ur = UB - 1;           // clamp (last block), results unused
        rowg[j] = g * H + ubase + ur;
        wrow[j] = Whh + (size_t)rowg[j] * H + ks * 400;
    }

    // update-role constants: unit u = w, batch = lane
    const bool updact = (w < UB);
    const int  uu = updact ? w : 0;
    float bias_r[4];
#pragma unroll
    for (int g = 0; g < 4; g++)
        bias_r[g] = __ldg(&bia[g * H + ubase + uu]);
    float creg = 0.0f;

    for (int s = 0; s < T; s++) {
        const int t  = dir ? (T - 1 - s) : s;
        const int ph = s & 1;

        // ---- stage h[ph] into smem (coalesced, conflict-free) ----
        const float4* hsrc4 = (const float4*)&g_hstate[ph][dir][0][0];
        for (int i = tid; i < 6400; i += 384) {
            int b = i / 200, kq = i - b * 200;
            float4 v = __ldcg(hsrc4 + i);
            *(float4*)(sh + b * SHF + kq * 4) = v;
        }
        if (LAYER == 0) {
            for (int i = tid; i < 32 * SXS; i += 384) {
                int b = i / SXS, k = i - b * SXS;
                sx[i] = (k < DIN) ? __ldg(&x[(t * B + b) * DIN + k]) : 0.0f;
            }
        }
        __syncthreads();

        // ---- 8 rows x own batch, k-slice 400, double-buffered weights ----
        ull acc[8];
#pragma unroll
        for (int j = 0; j < 8; j++) acc[j] = 0;

        const float* hb = sh + lane * SHF + ks * 400;
        float4 wn[8];
#pragma unroll
        for (int j = 0; j < 8; j++) wn[j] = __ldg((const float4*)(wrow[j]));

        for (int k = 0; k < 400; k += 4) {
            float4 wc[8];
#pragma unroll
            for (int j = 0; j < 8; j++) wc[j] = wn[j];
            const int kn = (k + 4 < 400) ? k + 4 : 0;
#pragma unroll
            for (int j = 0; j < 8; j++)
                wn[j] = __ldg((const float4*)(wrow[j] + kn));
            float4 hv = *(const float4*)(hb + k);
            ull hlo = ((const ull*)&hv)[0], hhi = ((const ull*)&hv)[1];
#pragma unroll
            for (int j = 0; j < 8; j++) {
                ffma2(acc[j], ((const ull*)&wc[j])[0], hlo);
                ffma2(acc[j], ((const ull*)&wc[j])[1], hhi);
            }
        }

        // input projection (layer 0): ks==1 warps, K = 52 (padded)
        if (LAYER == 0 && ks == 1) {
            const float* hb2 = sx + lane * SXS;
#pragma unroll
            for (int k = 0; k < SXS; k += 4) {
                float4 hv = *(const float4*)(hb2 + k);
                ull hlo = ((const ull*)&hv)[0], hhi = ((const ull*)&hv)[1];
#pragma unroll
                for (int j = 0; j < 8; j++) {
                    float4 wv = __ldg((const float4*)((const float*)g_Wp
                                 + (size_t)dir * (4 * H * SXS)
                                 + (size_t)rowg[j] * SXS + k));
                    ffma2(acc[j], ((const ull*)&wv)[0], hlo);
                    ffma2(acc[j], ((const ull*)&wv)[1], hhi);
                }
            }
        }

        // ---- write pair-partials (ull) ----
#pragma unroll
        for (int j = 0; j < 8; j++)
            sredU[(ks * 48 + rg * 8 + j) * 32 + lane] = acc[j];
        __syncthreads();

        // ---- cell update: unit w, batch lane ----
        if (updact) {
            const int ug = ubase + w;
            float e[4];
#pragma unroll
            for (int g = 0; g < 4; g++) {
                int r = g * 12 + w;
                e[g] = hadd(sredU[r * 32 + lane])
                     + hadd(sredU[(48 + r) * 32 + lane]) + bias_r[g];
                if (LAYER == 1)
                    e[g] += __ldg(&g_xs1[dir][t][g * H + ug][lane]);
            }
            float cn = sigm(e[1]) * creg + sigm(e[0]) * tanhf(e[2]);
            float hn = sigm(e[3]) * tanhf(cn);
            creg = cn;
            g_hstate[ph ^ 1][dir][lane][ug] = hn;
            if (LAYER == 0) g_h1[t][lane][dir * H + ug] = hn;
            else            g_h2[t][lane][dir * H + ug] = hn;
        }

        __syncthreads();
        if (s < T - 1) {
            if (tid == 0) {
                __threadfence();
                atomicAdd(&g_bar[LAYER][s], 1);
                while (((volatile int*)g_bar[LAYER])[s] < NBLK) __nanosleep(64);
                __threadfence();
            }
            __syncthreads();
        }
    }
}

// ---------------- xs1 = Wih1 @ h1 : 8 rows x (2 t x 4 b) per thread ----------
__global__ void __launch_bounds__(128, 2) xs1_gemm(
    const float* __restrict__ Wf, const float* __restrict__ Wb)
{
    const int gt = blockIdx.x, tp = blockIdx.y, dir = blockIdx.z;
    const float* __restrict__ W = dir ? Wb : Wf;
    const int t0 = tp * 2;

    __shared__ alignas(16) float sh[2][32 * 164];

    const int tid = threadIdx.x;
    const int rowg = tid >> 3, bq = tid & 7;
    const int r0 = gt * 128 + rowg * 8;
    const float* wbase = W + (size_t)r0 * (2 * H);

    ull acc[64];
#pragma unroll
    for (int j = 0; j < 64; j++) acc[j] = 0;

    for (int k0 = 0; k0 < 2 * H; k0 += 160) {
        __syncthreads();
        for (int i2 = tid; i2 < 2560; i2 += 128) {
            int tq = i2 / 1280, rem = i2 - tq * 1280;
            int b = rem / 40, kq = rem - b * 40;
            *(float4*)&sh[tq][b * 164 + kq * 4] =
                __ldg((const float4*)(&g_h1[t0 + tq][b][k0 + kq * 4]));
        }
        __syncthreads();
        for (int k = 0; k < 160; k += 4) {
            float4 hv[8];
#pragma unroll
            for (int tq = 0; tq < 2; tq++)
#pragma unroll
                for (int i = 0; i < 4; i++)
                    hv[tq * 4 + i] = *(const float4*)&sh[tq][(bq + 8 * i) * 164 + k];
#pragma unroll
            for (int j = 0; j < 8; j++) {
                float4 wv = __ldg((const float4*)(wbase + j * (2 * H) + k0 + k));
                ull wlo = ((const ull*)&wv)[0], whi = ((const ull*)&wv)[1];
#pragma unroll
                for (int c = 0; c < 8; c++) {
                    ffma2(acc[j * 8 + c], wlo, ((const ull*)&hv[c])[0]);
                    ffma2(acc[j * 8 + c], whi, ((const ull*)&hv[c])[1]);
                }
            }
        }
    }
#pragma unroll
    for (int j = 0; j < 8; j++)
#pragma unroll
        for (int tq = 0; tq < 2; tq++)
#pragma unroll
            for (int i = 0; i < 4; i++)
                g_xs1[dir][t0 + tq][r0 + j][bq + 8 * i] = hadd(acc[j * 8 + tq * 4 + i]);
}

// ---------------- logits -> softmax-folded atan2 -> angles ----------------
__global__ void __launch_bounds__(640) logits_angles(
    const float* __restrict__ Wl, const float* __restrict__ bl,
    const float* __restrict__ alphabet)
{
    const int t = blockIdx.x, tid = threadIdx.x;
    __shared__ float sl[32][21];
    __shared__ float ssin[20][3], scos[20][3];

    if (tid < 60) {
        int a = tid / 3, j = tid % 3;
        float v = alphabet[tid];
        ssin[a][j] = sinf(v); scos[a][j] = cosf(v);
    }
    {
        int a = tid >> 5, b = tid & 31;
        float acc = 0.0f;
        for (int k = 0; k < 2 * H; k += 4) {
            float4 hv = __ldg((const float4*)&g_h2[t][b][k]);
            float4 wv = __ldg((const float4*)&Wl[a * 2 * H + k]);
            acc += hv.x * wv.x + hv.y * wv.y + hv.z * wv.z + hv.w * wv.w;
        }
        sl[b][a] = acc + __ldg(&bl[a]);
    }
    __syncthreads();

    if (tid < 32) {
        int b = tid;
        float m = -1e30f;
#pragma unroll
        for (int a = 0; a < 20; a++) m = fmaxf(m, sl[b][a]);
        float ys[3] = {0, 0, 0}, xc[3] = {0, 0, 0};
#pragma unroll
        for (int a = 0; a < 20; a++) {
            float e = expf(sl[b][a] - m);
#pragma unroll
            for (int j = 0; j < 3; j++) { ys[j] += e * ssin[a][j]; xc[j] += e * scos[a][j]; }
        }
#pragma unroll
        for (int j = 0; j < 3; j++) g_ang[t][b][j] = atan2f(ys[j], xc[j]);
    }
}

// ---------------- NeRF coordinate extension ----------------
__global__ void coord_scan_kernel(float* __restrict__ out)
{
    const int b = threadIdx.x;
    const float rl[3] = {1.458f, 1.525f, 1.33f};
    const float th[3] = {2.124f, 1.941f, 2.028f};
    float rct[3], rst[3];
#pragma unroll
    for (int j = 0; j < 3; j++) { rct[j] = rl[j] * cosf(th[j]); rst[j] = rl[j] * sinf(th[j]); }

    float ax = 0.f, ay = 0.f, az = 0.f;
    float bx = 1.458f, by = 0.f, bz = 0.f;
    float cx = 2.f, cy = 1.f, cz = 0.f;

    for (int n = 0; n < 3 * T; n++) {
        int tt = n / 3, j = n - 3 * tt;
        float phi = g_ang[tt][b][j];
        float bcx = cx - bx, bcy = cy - by, bcz = cz - bz;
        float inv = rsqrtf(bcx * bcx + bcy * bcy + bcz * bcz);
        bcx *= inv; bcy *= inv; bcz *= inv;
        float abx = bx - ax, aby = by - ay, abz = bz - az;
        float nx = aby * bcz - abz * bcy;
        float ny = abz * bcx - abx * bcz;
        float nz = abx * bcy - aby * bcx;
        inv = rsqrtf(nx * nx + ny * ny + nz * nz);
        nx *= inv; ny *= inv; nz *= inv;
        float mx = ny * bcz - nz * bcy;
        float my = nz * bcx - nx * bcz;
        float mz = nx * bcy - ny * bcx;
        float sphi, cphi;
        __sincosf(phi, &sphi, &cphi);
        float dx = cx - rct[j] * bcx + rst[j] * (cphi * mx + sphi * nx);
        float dy = cy - rct[j] * bcy + rst[j] * (cphi * my + sphi * ny);
        float dz = cz - rct[j] * bcz + rst[j] * (cphi * mz + sphi * nz);
        float* o = out + (n * B + b) * 3;
        o[0] = dx; o[1] = dy; o[2] = dz;
        ax = bx; ay = by; az = bz;
        bx = cx; by = cy; bz = cz;
        cx = dx; cy = dy; cz = dz;
    }
}

// ---------------- launch (8 graph nodes) ----------------
extern "C" void kernel_launch(void* const* d_in, const int* in_sizes, int n_in,
                              void* d_out, int out_size)
{
    const float* x      = (const float*)d_in[0];
    const float* Wih_f0 = (const float*)d_in[1];
    const float* Whh_f0 = (const float*)d_in[2];
    const float* b_f0   = (const float*)d_in[3];
    const float* Wih_b0 = (const float*)d_in[4];
    const float* Whh_b0 = (const float*)d_in[5];
    const float* b_b0   = (const float*)d_in[6];
    const float* Wih_f1 = (const float*)d_in[7];
    const float* Whh_f1 = (const float*)d_in[8];
    const float* b_f1   = (const float*)d_in[9];
    const float* Wih_b1 = (const float*)d_in[10];
    const float* Whh_b1 = (const float*)d_in[11];
    const float* b_b1   = (const float*)d_in[12];
    const float* Wl     = (const float*)d_in[13];
    const float* bl     = (const float*)d_in[14];
    const float* alpha  = (const float*)d_in[15];
    float* out = (float*)d_out;

    const int smem_rec = (32 * SHF + 32 * SXS + 2 * 48 * 32 * 2) * (int)sizeof(float);
    cudaFuncSetAttribute(lstm_persist<0>, cudaFuncAttributeMaxDynamicSharedMemorySize, smem_rec);
    cudaFuncSetAttribute(lstm_persist<1>, cudaFuncAttributeMaxDynamicSharedMemorySize, smem_rec);

    prep_wp<<<1300, 256>>>(Wih_f0, Wih_b0);
    zero_kernel<<<400, 256>>>(1);
    lstm_persist<0><<<NBLK, 384, smem_rec>>>(x, Whh_f0, b_f0, Whh_b0, b_b0);
    xs1_gemm<<<dim3(25, 256, 2), 128>>>(Wih_f1, Wih_b1);
    zero_kernel<<<400, 256>>>(0);
    lstm_persist<1><<<NBLK, 384, smem_rec>>>(nullptr, Whh_f1, b_f1, Whh_b1, b_b1);
    logits_angles<<<T, 640>>>(Wl, bl, alpha);
    coord_scan_kernel<<<1, 32>>>(out);
}

// round 12
// speedup vs baseline: 1.3853x; 1.3853x over previous
#include <cuda_runtime.h>
#include <math.h>

constexpr int T = 512, B = 32, DIN = 41, H = 800;
constexpr int UPB = 12;                 // units per block
constexpr int BPD = 67;                 // blocks per direction (66 full + 1x8)
constexpr int NBLK = 2 * BPD;           // 134 persistent blocks (1 wave on 148 SMs)
constexpr int SHC = 404;                // h chunk row stride floats (101 x 16B, odd)
constexpr int SXS = 52;                 // padded input K (13 x 16B, odd)
typedef unsigned long long ull;

// ---------------- scratch ----------------
__device__ float g_hstate[2][2][B][H];  // [phase][dir][b][k]
__device__ float g_h1[T][B][2 * H];
__device__ float g_h2[T][B][2 * H];
__device__ float g_xs1[2][T][4 * H][B];
__device__ float g_Wp[2][4 * H][SXS];   // zero-padded Wih layer0
__device__ float g_ang[T][B][3];
__device__ int   g_bar[2][T];

// ---------------- helpers ----------------
__device__ __forceinline__ void ffma2(ull& d, ull a, ull b) {
    asm("fma.rn.f32x2 %0, %1, %2, %0;" : "+l"(d) : "l"(a), "l"(b));
}
__device__ __forceinline__ float hadd(ull v) {
    float lo, hi;
    asm("mov.b64 {%0,%1}, %2;" : "=f"(lo), "=f"(hi) : "l"(v));
    return lo + hi;
}
__device__ __forceinline__ float sigm(float x) { return 1.0f / (1.0f + expf(-x)); }

// ---------------- init ----------------
__global__ void zero_kernel(int zero_bar) {
    int i = blockIdx.x * blockDim.x + threadIdx.x;
    if (i < 2 * 2 * B * H) ((float*)g_hstate)[i] = 0.0f;
    if (zero_bar && i < 2 * T) ((int*)g_bar)[i] = 0;
}

__global__ void prep_wp(const float* __restrict__ Wf, const float* __restrict__ Wb) {
    int i = blockIdx.x * blockDim.x + threadIdx.x;
    if (i >= 2 * 4 * H * SXS) return;
    int dir = i / (4 * H * SXS);
    int rem = i % (4 * H * SXS);
    int r = rem / SXS, k = rem % SXS;
    const float* W = dir ? Wb : Wf;
    ((float*)g_Wp)[i] = (k < DIN) ? W[r * DIN + k] : 0.0f;
}

// ---------------- persistent bi-LSTM layer: weights resident in SMEM ----------
// 134 blocks x 384 threads = 12 warps. Warp w -> (rg = w%6, ks = w/6).
// SMEM: sw[48][800] weights (preloaded ONCE, reused 512 steps),
//       swx[48][52], sx[32][52], sh[32][404] h-chunk (k chunked x2 in time),
//       sred (2-way k-split partials) OVERLAYS sh (disjoint lifetime).
// Warp reads weights as uniform LDS broadcasts; h via conflict-free LDS.128.
// Update role: warp w = unit, lane = batch; c stays in a register.
template <int LAYER>
__global__ void __launch_bounds__(384, 1) lstm_persist(
    const float* __restrict__ x,
    const float* __restrict__ Whh_f, const float* __restrict__ b_f,
    const float* __restrict__ Whh_b, const float* __restrict__ b_b)
{
    extern __shared__ float smem[];
    float* sw  = smem;                       // [48][800]
    float* swx = smem + 48 * 800;            // [48][52]
    float* sx  = swx + 48 * SXS;             // [32][52]
    float* sh  = sx + 32 * SXS;              // [32][404] chunk buffer
    ull*  sredU = (ull*)sh;                  // overlay [2ks][48r][32b]

    const int tid  = threadIdx.x;
    const int w    = tid >> 5;               // warp 0..11
    const int lane = tid & 31;               // batch
    const int rg   = w % 6, ks = w / 6;

    const int blk  = blockIdx.x;
    const int dir  = (blk >= BPD);
    const int ublk = dir ? blk - BPD : blk;
    const int UB    = (800 - ublk * UPB < UPB) ? (800 - ublk * UPB) : UPB;
    const int ubase = ublk * UPB;

    const float* __restrict__ Whh = dir ? Whh_b : Whh_f;
    const float* __restrict__ bia = dir ? b_b : b_f;

    // ---- preload recurrent weights into smem (once, reused 512 steps) ----
    for (int i = tid; i < 48 * 200; i += 384) {
        int r = i / 200, kq = i - r * 200;
        int g = r / 12, ur = r - g * 12;
        if (ur >= UB) ur = UB - 1;           // clamp (last block), results unused
        float4 v = __ldg((const float4*)(Whh + (size_t)(g * H + ubase + ur) * H + kq * 4));
        *(float4*)(sw + r * 800 + kq * 4) = v;
    }
    if (LAYER == 0) {
        for (int i = tid; i < 48 * 13; i += 384) {
            int r = i / 13, kq = i - r * 13;
            int g = r / 12, ur = r - g * 12;
            if (ur >= UB) ur = UB - 1;
            float4 v = __ldg((const float4*)(&g_Wp[dir][g * H + ubase + ur][kq * 4]));
            *(float4*)(swx + r * SXS + kq * 4) = v;
        }
    }
    __syncthreads();

    // update-role constants: unit = warp id, batch = lane
    const bool updact = (w < UB);
    const int  uu = updact ? w : 0;
    float bias_r[4];
#pragma unroll
    for (int g = 0; g < 4; g++)
        bias_r[g] = __ldg(&bia[g * H + ubase + uu]);
    float creg = 0.0f;

    for (int s = 0; s < T; s++) {
        const int t  = dir ? (T - 1 - s) : s;
        const int ph = s & 1;
        const float4* hsrc4 = (const float4*)&g_hstate[ph][dir][0][0];

        ull acc[8];
#pragma unroll
        for (int j = 0; j < 8; j++) acc[j] = 0;

        // ---- two k-chunks of 400; warp covers its ks-half of each chunk ----
#pragma unroll
        for (int c = 0; c < 2; c++) {
            for (int i = tid; i < 3200; i += 384) {
                int b = i / 100, kq = i - b * 100;
                float4 v = __ldcg(hsrc4 + b * 200 + c * 100 + kq);
                *(float4*)(sh + b * SHC + kq * 4) = v;
            }
            if (LAYER == 0 && c == 0) {
                for (int i = tid; i < 32 * SXS; i += 384) {
                    int b = i / SXS, k = i - b * SXS;
                    sx[i] = (k < DIN) ? __ldg(&x[(t * B + b) * DIN + k]) : 0.0f;
                }
            }
            __syncthreads();

            const float* hb = sh + lane * SHC + ks * 200;
            const float* wb = sw + (rg * 8) * 800 + c * 400 + ks * 200;
#pragma unroll 2
            for (int k = 0; k < 200; k += 4) {
                float4 hv = *(const float4*)(hb + k);
                ull hlo = ((const ull*)&hv)[0], hhi = ((const ull*)&hv)[1];
#pragma unroll
                for (int j = 0; j < 8; j++) {
                    float4 wv = *(const float4*)(wb + j * 800 + k);   // uniform bcast
                    ffma2(acc[j], ((const ull*)&wv)[0], hlo);
                    ffma2(acc[j], ((const ull*)&wv)[1], hhi);
                }
            }
            __syncthreads();   // chunk fully consumed (also guards red overlay)
        }

        // input projection (layer 0): ks==1 warps, K = 52 (padded)
        if (LAYER == 0 && ks == 1) {
            const float* hb2 = sx + lane * SXS;
#pragma unroll
            for (int k = 0; k < SXS; k += 4) {
                float4 hv = *(const float4*)(hb2 + k);
                ull hlo = ((const ull*)&hv)[0], hhi = ((const ull*)&hv)[1];
#pragma unroll
                for (int j = 0; j < 8; j++) {
                    float4 wv = *(const float4*)(swx + (rg * 8 + j) * SXS + k);
                    ffma2(acc[j], ((const ull*)&wv)[0], hlo);
                    ffma2(acc[j], ((const ull*)&wv)[1], hhi);
                }
            }
        }

        // ---- write pair-partials (overlay on sh; safe post-sync) ----
#pragma unroll
        for (int j = 0; j < 8; j++)
            sredU[(ks * 48 + rg * 8 + j) * 32 + lane] = acc[j];
        __syncthreads();

        // ---- cell update: unit w, batch lane ----
        if (updact) {
            const int ug = ubase + w;
            float e[4];
#pragma unroll
            for (int g = 0; g < 4; g++) {
                int r = g * 12 + w;
                e[g] = hadd(sredU[r * 32 + lane])
                     + hadd(sredU[(48 + r) * 32 + lane]) + bias_r[g];
                if (LAYER == 1)
                    e[g] += __ldg(&g_xs1[dir][t][g * H + ug][lane]);
            }
            float cn = sigm(e[1]) * creg + sigm(e[0]) * tanhf(e[2]);
            float hn = sigm(e[3]) * tanhf(cn);
            creg = cn;
            g_hstate[ph ^ 1][dir][lane][ug] = hn;
            if (LAYER == 0) g_h1[t][lane][dir * H + ug] = hn;
            else            g_h2[t][lane][dir * H + ug] = hn;
        }

        __syncthreads();
        if (s < T - 1) {
            if (tid == 0) {
                __threadfence();
                atomicAdd(&g_bar[LAYER][s], 1);
                while (((volatile int*)g_bar[LAYER])[s] < NBLK) __nanosleep(64);
                __threadfence();
            }
            __syncthreads();
        }
    }
}

// ---------------- xs1 = Wih1 @ h1 : 8 rows x (2 t x 4 b) per thread ----------
__global__ void __launch_bounds__(128, 2) xs1_gemm(
    const float* __restrict__ Wf, const float* __restrict__ Wb)
{
    const int gt = blockIdx.x, tp = blockIdx.y, dir = blockIdx.z;
    const float* __restrict__ W = dir ? Wb : Wf;
    const int t0 = tp * 2;

    __shared__ alignas(16) float sh[2][32 * 164];

    const int tid = threadIdx.x;
    const int rowg = tid >> 3, bq = tid & 7;
    const int r0 = gt * 128 + rowg * 8;
    const float* wbase = W + (size_t)r0 * (2 * H);

    ull acc[64];
#pragma unroll
    for (int j = 0; j < 64; j++) acc[j] = 0;

    for (int k0 = 0; k0 < 2 * H; k0 += 160) {
        __syncthreads();
        for (int i2 = tid; i2 < 2560; i2 += 128) {
            int tq = i2 / 1280, rem = i2 - tq * 1280;
            int b = rem / 40, kq = rem - b * 40;
            *(float4*)&sh[tq][b * 164 + kq * 4] =
                __ldg((const float4*)(&g_h1[t0 + tq][b][k0 + kq * 4]));
        }
        __syncthreads();
        for (int k = 0; k < 160; k += 4) {
            float4 hv[8];
#pragma unroll
            for (int tq = 0; tq < 2; tq++)
#pragma unroll
                for (int i = 0; i < 4; i++)
                    hv[tq * 4 + i] = *(const float4*)&sh[tq][(bq + 8 * i) * 164 + k];
#pragma unroll
            for (int j = 0; j < 8; j++) {
                float4 wv = __ldg((const float4*)(wbase + j * (2 * H) + k0 + k));
                ull wlo = ((const ull*)&wv)[0], whi = ((const ull*)&wv)[1];
#pragma unroll
                for (int c = 0; c < 8; c++) {
                    ffma2(acc[j * 8 + c], wlo, ((const ull*)&hv[c])[0]);
                    ffma2(acc[j * 8 + c], whi, ((const ull*)&hv[c])[1]);
                }
            }
        }
    }
#pragma unroll
    for (int j = 0; j < 8; j++)
#pragma unroll
        for (int tq = 0; tq < 2; tq++)
#pragma unroll
            for (int i = 0; i < 4; i++)
                g_xs1[dir][t0 + tq][r0 + j][bq + 8 * i] = hadd(acc[j * 8 + tq * 4 + i]);
}

// ---------------- logits -> softmax-folded atan2 -> angles ----------------
__global__ void __launch_bounds__(640) logits_angles(
    const float* __restrict__ Wl, const float* __restrict__ bl,
    const float* __restrict__ alphabet)
{
    const int t = blockIdx.x, tid = threadIdx.x;
    __shared__ float sl[32][21];
    __shared__ float ssin[20][3], scos[20][3];

    if (tid < 60) {
        int a = tid / 3, j = tid % 3;
        float v = alphabet[tid];
        ssin[a][j] = sinf(v); scos[a][j] = cosf(v);
    }
    {
        int a = tid >> 5, b = tid & 31;
        float acc = 0.0f;
        for (int k = 0; k < 2 * H; k += 4) {
            float4 hv = __ldg((const float4*)&g_h2[t][b][k]);
            float4 wv = __ldg((const float4*)&Wl[a * 2 * H + k]);
            acc += hv.x * wv.x + hv.y * wv.y + hv.z * wv.z + hv.w * wv.w;
        }
        sl[b][a] = acc + __ldg(&bl[a]);
    }
    __syncthreads();

    if (tid < 32) {
        int b = tid;
        float m = -1e30f;
#pragma unroll
        for (int a = 0; a < 20; a++) m = fmaxf(m, sl[b][a]);
        float ys[3] = {0, 0, 0}, xc[3] = {0, 0, 0};
#pragma unroll
        for (int a = 0; a < 20; a++) {
            float e = expf(sl[b][a] - m);
#pragma unroll
            for (int j = 0; j < 3; j++) { ys[j] += e * ssin[a][j]; xc[j] += e * scos[a][j]; }
        }
#pragma unroll
        for (int j = 0; j < 3; j++) g_ang[t][b][j] = atan2f(ys[j], xc[j]);
    }
}

// ---------------- NeRF coordinate extension ----------------
__global__ void coord_scan_kernel(float* __restrict__ out)
{
    const int b = threadIdx.x;
    const float rl[3] = {1.458f, 1.525f, 1.33f};
    const float th[3] = {2.124f, 1.941f, 2.028f};
    float rct[3], rst[3];
#pragma unroll
    for (int j = 0; j < 3; j++) { rct[j] = rl[j] * cosf(th[j]); rst[j] = rl[j] * sinf(th[j]); }

    float ax = 0.f, ay = 0.f, az = 0.f;
    float bx = 1.458f, by = 0.f, bz = 0.f;
    float cx = 2.f, cy = 1.f, cz = 0.f;

    for (int n = 0; n < 3 * T; n++) {
        int tt = n / 3, j = n - 3 * tt;
        float phi = g_ang[tt][b][j];
        float bcx = cx - bx, bcy = cy - by, bcz = cz - bz;
        float inv = rsqrtf(bcx * bcx + bcy * bcy + bcz * bcz);
        bcx *= inv; bcy *= inv; bcz *= inv;
        float abx = bx - ax, aby = by - ay, abz = bz - az;
        float nx = aby * bcz - abz * bcy;
        float ny = abz * bcx - abx * bcz;
        float nz = abx * bcy - aby * bcx;
        inv = rsqrtf(nx * nx + ny * ny + nz * nz);
        nx *= inv; ny *= inv; nz *= inv;
        float mx = ny * bcz - nz * bcy;
        float my = nz * bcx - nx * bcz;
        float mz = nx * bcy - ny * bcx;
        float sphi, cphi;
        __sincosf(phi, &sphi, &cphi);
        float dx = cx - rct[j] * bcx + rst[j] * (cphi * mx + sphi * nx);
        float dy = cy - rct[j] * bcy + rst[j] * (cphi * my + sphi * ny);
        float dz = cz - rct[j] * bcz + rst[j] * (cphi * mz + sphi * nz);
        float* o = out + (n * B + b) * 3;
        o[0] = dx; o[1] = dy; o[2] = dz;
        ax = bx; ay = by; az = bz;
        bx = cx; by = cy; bz = cz;
        cx = dx; cy = dy; cz = dz;
    }
}

// ---------------- launch (8 graph nodes) ----------------
extern "C" void kernel_launch(void* const* d_in, const int* in_sizes, int n_in,
                              void* d_out, int out_size)
{
    const float* x      = (const float*)d_in[0];
    const float* Wih_f0 = (const float*)d_in[1];
    const float* Whh_f0 = (const float*)d_in[2];
    const float* b_f0   = (const float*)d_in[3];
    const float* Wih_b0 = (const float*)d_in[4];
    const float* Whh_b0 = (const float*)d_in[5];
    const float* b_b0   = (const float*)d_in[6];
    const float* Wih_f1 = (const float*)d_in[7];
    const float* Whh_f1 = (const float*)d_in[8];
    const float* b_f1   = (const float*)d_in[9];
    const float* Wih_b1 = (const float*)d_in[10];
    const float* Whh_b1 = (const float*)d_in[11];
    const float* b_b1   = (const float*)d_in[12];
    const float* Wl     = (const float*)d_in[13];
    const float* bl     = (const float*)d_in[14];
    const float* alpha  = (const float*)d_in[15];
    float* out = (float*)d_out;

    // smem: 48*800 + 48*52 + 32*52 + 32*404 floats = 221,952 bytes
    const int smem_rec = (48 * 800 + 48 * SXS + 32 * SXS + 32 * SHC) * (int)sizeof(float);
    cudaFuncSetAttribute(lstm_persist<0>, cudaFuncAttributeMaxDynamicSharedMemorySize, smem_rec);
    cudaFuncSetAttribute(lstm_persist<1>, cudaFuncAttributeMaxDynamicSharedMemorySize, smem_rec);

    prep_wp<<<1300, 256>>>(Wih_f0, Wih_b0);
    zero_kernel<<<400, 256>>>(1);
    lstm_persist<0><<<NBLK, 384, smem_rec>>>(x, Whh_f0, b_f0, Whh_b0, b_b0);
    xs1_gemm<<<dim3(25, 256, 2), 128>>>(Wih_f1, Wih_b1);
    zero_kernel<<<400, 256>>>(0);
    lstm_persist<1><<<NBLK, 384, smem_rec>>>(nullptr, Whh_f1, b_f1, Whh_b1, b_b1);
    logits_angles<<<T, 640>>>(Wl, bl, alpha);
    coord_scan_kernel<<<1, 32>>>(out);
}

// round 13
// speedup vs baseline: 1.4406x; 1.0399x over previous
#include <cuda_runtime.h>
#include <math.h>

constexpr int T = 512, B = 32, DIN = 41, H = 800;
constexpr int UPB = 12;                 // units per block
constexpr int BPD = 67;                 // blocks per direction
constexpr int NBLK = 2 * BPD;           // 134 persistent blocks (1 wave)
constexpr int SXS = 52;                 // padded input K
constexpr int SWF  = 48 * 800;          // smem weight slab (floats)
constexpr int SWXF = 48 * SXS;
constexpr int SXF  = 32 * SXS;
constexpr int BUFSTR = 204;             // chunk buf row stride (51 x 16B, odd)
constexpr int BUFF = 32 * BUFSTR;       // 6528 floats per chunk buffer
typedef unsigned long long ull;

// ---------------- scratch ----------------
__device__ float g_hstate[2][2][B][H];  // [phase][dir][b][k]
__device__ float g_h1[T][B][2 * H];
__device__ float g_h2[T][B][2 * H];
__device__ float g_xs1[2][T][4 * H][B];
__device__ float g_Wp[2][4 * H][SXS];
__device__ float g_ang[T][B][3];
__device__ int   g_bar[2][2][T];        // [layer][dir][step]

// ---------------- helpers ----------------
__device__ __forceinline__ void ffma2(ull& d, ull a, ull b) {
    asm("fma.rn.f32x2 %0, %1, %2, %0;" : "+l"(d) : "l"(a), "l"(b));
}
__device__ __forceinline__ float hadd(ull v) {
    float lo, hi;
    asm("mov.b64 {%0,%1}, %2;" : "=f"(lo), "=f"(hi) : "l"(v));
    return lo + hi;
}
__device__ __forceinline__ float sigm(float x) { return 1.0f / (1.0f + expf(-x)); }
__device__ __forceinline__ void cpasync16(unsigned dst, const void* src) {
    asm volatile("cp.async.cg.shared.global [%0], [%1], 16;" :: "r"(dst), "l"(src));
}
#define CP_COMMIT() asm volatile("cp.async.commit_group;")
#define CP_WAIT(n)  asm volatile("cp.async.wait_group %0;" :: "n"(n))

// ---------------- init ----------------
__global__ void zero_kernel() {
    int i = blockIdx.x * blockDim.x + threadIdx.x;
    if (i < 2 * 2 * B * H) ((float*)g_hstate)[i] = 0.0f;
    if (i < 2 * 2 * T) ((int*)g_bar)[i] = 0;
}
__global__ void zero_state_only() {
    int i = blockIdx.x * blockDim.x + threadIdx.x;
    if (i < 2 * 2 * B * H) ((float*)g_hstate)[i] = 0.0f;
}

__global__ void prep_wp(const float* __restrict__ Wf, const float* __restrict__ Wb) {
    int i = blockIdx.x * blockDim.x + threadIdx.x;
    if (i >= 2 * 4 * H * SXS) return;
    int dir = i / (4 * H * SXS);
    int rem = i % (4 * H * SXS);
    int r = rem / SXS, k = rem % SXS;
    const float* W = dir ? Wb : Wf;
    ((float*)g_Wp)[i] = (k < DIN) ? W[r * DIN + k] : 0.0f;
}

// ---------------- persistent bi-LSTM: smem weights + cp.async h pipeline ----
// 134 blocks x 384 thr = 12 warps. Warp w -> (rg = w%6 rows-of-8, ks = w/6).
// h per step: 4 chunks of 200 k, double-buffered cp.async (stage hidden).
// sred (2-way k-split partials) overlays chunk buffer 0.
template <int LAYER>
__global__ void __launch_bounds__(384, 1) lstm_persist(
    const float* __restrict__ x,
    const float* __restrict__ Whh_f, const float* __restrict__ b_f,
    const float* __restrict__ Whh_b, const float* __restrict__ b_b)
{
    extern __shared__ float smem[];
    float* sw  = smem;                       // [48][800]
    float* swx = smem + SWF;                 // [48][52]
    float* sx  = swx + SWXF;                 // [32][52]
    float* shb = sx + SXF;                   // 2 x [32][204] chunk buffers
    ull*  sredU = (ull*)shb;                 // overlay on buffer 0
    const unsigned bufu = (unsigned)__cvta_generic_to_shared(shb);

    const int tid  = threadIdx.x;
    const int w    = tid >> 5;
    const int lane = tid & 31;
    const int rg   = w % 6, ks = w / 6;

    const int blk  = blockIdx.x;
    const int dir  = (blk >= BPD);
    const int ublk = dir ? blk - BPD : blk;
    const int UB    = (800 - ublk * UPB < UPB) ? (800 - ublk * UPB) : UPB;
    const int ubase = ublk * UPB;

    const float* __restrict__ Whh = dir ? Whh_b : Whh_f;
    const float* __restrict__ bia = dir ? b_b : b_f;

    // ---- preload weights into smem (once, reused 512 steps) ----
    for (int i = tid; i < 48 * 200; i += 384) {
        int r = i / 200, kq = i - r * 200;
        int g = r / 12, ur = r - g * 12;
        if (ur >= UB) ur = UB - 1;
        float4 v = __ldg((const float4*)(Whh + (size_t)(g * H + ubase + ur) * H + kq * 4));
        *(float4*)(sw + r * 800 + kq * 4) = v;
    }
    if (LAYER == 0) {
        for (int i = tid; i < 48 * 13; i += 384) {
            int r = i / 13, kq = i - r * 13;
            int g = r / 12, ur = r - g * 12;
            if (ur >= UB) ur = UB - 1;
            float4 v = __ldg((const float4*)(&g_Wp[dir][g * H + ubase + ur][kq * 4]));
            *(float4*)(swx + r * SXS + kq * 4) = v;
        }
    }
    __syncthreads();

    const bool updact = (w < UB);
    const int  uu = updact ? w : 0;
    float bias_r[4];
#pragma unroll
    for (int g = 0; g < 4; g++)
        bias_r[g] = __ldg(&bia[g * H + ubase + uu]);
    float creg = 0.0f;

#define ISSUE_CHUNK(c, bsel)                                                     \
    do {                                                                         \
        for (int i_ = tid; i_ < 1600; i_ += 384) {                               \
            int b_ = i_ / 50, q_ = i_ - b_ * 50;                                 \
            cpasync16(bufu + (unsigned)((bsel) * BUFF + b_ * BUFSTR + q_ * 4) * 4u, \
                      hsrc4 + b_ * 200 + (c) * 50 + q_);                         \
        }                                                                        \
        CP_COMMIT();                                                             \
    } while (0)

#define COMPUTE_CHUNK(c, bsel)                                                   \
    do {                                                                         \
        const float* hb_ = shb + (bsel) * BUFF + lane * BUFSTR + ks * 100;       \
        const float* wb_ = sw + (rg * 8) * 800 + (c) * 200 + ks * 100;           \
        _Pragma("unroll 5")                                                      \
        for (int k_ = 0; k_ < 100; k_ += 4) {                                    \
            float4 hv_ = *(const float4*)(hb_ + k_);                             \
            ull hlo_ = ((const ull*)&hv_)[0], hhi_ = ((const ull*)&hv_)[1];      \
            _Pragma("unroll")                                                    \
            for (int j_ = 0; j_ < 8; j_++) {                                     \
                float4 wv_ = *(const float4*)(wb_ + j_ * 800 + k_);              \
                ffma2(acc[j_], ((const ull*)&wv_)[0], hlo_);                     \
                ffma2(acc[j_], ((const ull*)&wv_)[1], hhi_);                     \
            }                                                                    \
        }                                                                        \
    } while (0)

    for (int s = 0; s < T; s++) {
        const int t  = dir ? (T - 1 - s) : s;
        const int ph = s & 1;
        const float4* hsrc4 = (const float4*)&g_hstate[ph][dir][0][0];

        ull acc[8];
#pragma unroll
        for (int j = 0; j < 8; j++) acc[j] = 0;

        ISSUE_CHUNK(0, 0);
        ISSUE_CHUNK(1, 1);
        if (LAYER == 0) {
            for (int i = tid; i < 32 * SXS; i += 384) {
                int b = i / SXS, k = i - b * SXS;
                sx[i] = (k < DIN) ? __ldg(&x[(t * B + b) * DIN + k]) : 0.0f;
            }
        }
        CP_WAIT(1); __syncthreads();              // c0 ready (+x drained)
        COMPUTE_CHUNK(0, 0);
        __syncthreads();                          // c0 consumers done
        ISSUE_CHUNK(2, 0);
        CP_WAIT(1); __syncthreads();              // c1 ready
        COMPUTE_CHUNK(1, 1);
        __syncthreads();                          // c1 consumers done
        ISSUE_CHUNK(3, 1);
        CP_WAIT(1); __syncthreads();              // c2 ready
        COMPUTE_CHUNK(2, 0);
        CP_WAIT(0); __syncthreads();              // c2 done + c3 ready
        COMPUTE_CHUNK(3, 1);

        if (LAYER == 0) {                          // input proj, split 24/28
            const float* hb2 = sx + lane * SXS;
            const int ka = ks ? 24 : 0, kb = ks ? 52 : 24;
            for (int k = ka; k < kb; k += 4) {
                float4 hv = *(const float4*)(hb2 + k);
                ull hlo = ((const ull*)&hv)[0], hhi = ((const ull*)&hv)[1];
#pragma unroll
                for (int j = 0; j < 8; j++) {
                    float4 wv = *(const float4*)(swx + (rg * 8 + j) * SXS + k);
                    ffma2(acc[j], ((const ull*)&wv)[0], hlo);
                    ffma2(acc[j], ((const ull*)&wv)[1], hhi);
                }
            }
        }

        // partials overlay buffer0 (its readers finished at prior sync)
#pragma unroll
        for (int j = 0; j < 8; j++)
            sredU[(ks * 48 + rg * 8 + j) * 32 + lane] = acc[j];
        __syncthreads();

        if (updact) {
            const int ug = ubase + w;
            float e[4];
#pragma unroll
            for (int g = 0; g < 4; g++) {
                int r = g * 12 + w;
                e[g] = hadd(sredU[r * 32 + lane])
                     + hadd(sredU[(48 + r) * 32 + lane]) + bias_r[g];
                if (LAYER == 1)
                    e[g] += __ldg(&g_xs1[dir][t][g * H + ug][lane]);
            }
            float cn = sigm(e[1]) * creg + sigm(e[0]) * tanhf(e[2]);
            float hn = sigm(e[3]) * tanhf(cn);
            creg = cn;
            g_hstate[ph ^ 1][dir][lane][ug] = hn;
            if (LAYER == 0) g_h1[t][lane][dir * H + ug] = hn;
            else            g_h2[t][lane][dir * H + ug] = hn;
        }

        __syncthreads();
        if (s < T - 1) {
            if (tid == 0) {
                __threadfence();
                atomicAdd(&g_bar[LAYER][dir][s], 1);
                while (((volatile int*)g_bar[LAYER][dir])[s] < BPD) {}
                __threadfence();
            }
            __syncthreads();
        }
    }
#undef ISSUE_CHUNK
#undef COMPUTE_CHUNK
}

// ---------------- xs1 = Wih1 @ h1 : cp.async double-buffered panels ---------
// 128 thr = (rowg<16, bq<8): 8 rows x (2 t x 4 b); dyn smem 2 x (2 x 32 x 164).
__global__ void __launch_bounds__(128, 2) xs1_gemm(
    const float* __restrict__ Wf, const float* __restrict__ Wb)
{
    extern __shared__ float shd[];
    const unsigned sbase = (unsigned)__cvta_generic_to_shared(shd);
    const int gt = blockIdx.x, tp = blockIdx.y, dir = blockIdx.z;
    const float* __restrict__ W = dir ? Wb : Wf;
    const int t0 = tp * 2;

    const int tid = threadIdx.x;
    const int rowg = tid >> 3, bq = tid & 7;
    const int r0 = gt * 128 + rowg * 8;
    const float* wbase = W + (size_t)r0 * (2 * H);

    ull acc[64];
#pragma unroll
    for (int j = 0; j < 64; j++) acc[j] = 0;

#define XS_ISSUE(p, bsel)                                                        \
    do {                                                                         \
        for (int i2_ = tid; i2_ < 2560; i2_ += 128) {                            \
            int tq_ = i2_ / 1280, rem_ = i2_ - tq_ * 1280;                       \
            int b_ = rem_ / 40, kq_ = rem_ - b_ * 40;                            \
            cpasync16(sbase + (unsigned)((bsel) * 10496 + tq_ * 5248 + b_ * 164 + kq_ * 4) * 4u, \
                      &g_h1[t0 + tq_][b_][(p) * 160 + kq_ * 4]);                 \
        }                                                                        \
        CP_COMMIT();                                                             \
    } while (0)

    XS_ISSUE(0, 0);
    CP_WAIT(0); __syncthreads();
    int buf = 0;
    for (int p = 0; p < 10; p++) {
        if (p < 9) XS_ISSUE(p + 1, buf ^ 1);
        const float* shp = shd + buf * 10496;
        const int k0 = p * 160;
        for (int k = 0; k < 160; k += 4) {
            float4 hv[8];
#pragma unroll
            for (int tq = 0; tq < 2; tq++)
#pragma unroll
                for (int i = 0; i < 4; i++)
                    hv[tq * 4 + i] = *(const float4*)&shp[tq * 5248 + (bq + 8 * i) * 164 + k];
#pragma unroll
            for (int j = 0; j < 8; j++) {
                float4 wv = __ldg((const float4*)(wbase + j * (2 * H) + k0 + k));
                ull wlo = ((const ull*)&wv)[0], whi = ((const ull*)&wv)[1];
#pragma unroll
                for (int c = 0; c < 8; c++) {
                    ffma2(acc[j * 8 + c], wlo, ((const ull*)&hv[c])[0]);
                    ffma2(acc[j * 8 + c], whi, ((const ull*)&hv[c])[1]);
                }
            }
        }
        CP_WAIT(0); __syncthreads();
        buf ^= 1;
    }
#undef XS_ISSUE
#pragma unroll
    for (int j = 0; j < 8; j++)
#pragma unroll
        for (int tq = 0; tq < 2; tq++)
#pragma unroll
            for (int i = 0; i < 4; i++)
                g_xs1[dir][t0 + tq][r0 + j][bq + 8 * i] = hadd(acc[j * 8 + tq * 4 + i]);
}

// ---------------- logits -> softmax-folded atan2 -> angles ----------------
__global__ void __launch_bounds__(640) logits_angles(
    const float* __restrict__ Wl, const float* __restrict__ bl,
    const float* __restrict__ alphabet)
{
    const int t = blockIdx.x, tid = threadIdx.x;
    __shared__ float sl[32][21];
    __shared__ float ssin[20][3], scos[20][3];

    if (tid < 60) {
        int a = tid / 3, j = tid % 3;
        float v = alphabet[tid];
        ssin[a][j] = sinf(v); scos[a][j] = cosf(v);
    }
    {
        int a = tid >> 5, b = tid & 31;
        float acc = 0.0f;
        for (int k = 0; k < 2 * H; k += 4) {
            float4 hv = __ldg((const float4*)&g_h2[t][b][k]);
            float4 wv = __ldg((const float4*)&Wl[a * 2 * H + k]);
            acc += hv.x * wv.x + hv.y * wv.y + hv.z * wv.z + hv.w * wv.w;
        }
        sl[b][a] = acc + __ldg(&bl[a]);
    }
    __syncthreads();

    if (tid < 32) {
        int b = tid;
        float m = -1e30f;
#pragma unroll
        for (int a = 0; a < 20; a++) m = fmaxf(m, sl[b][a]);
        float ys[3] = {0, 0, 0}, xc[3] = {0, 0, 0};
#pragma unroll
        for (int a = 0; a < 20; a++) {
            float e = expf(sl[b][a] - m);
#pragma unroll
            for (int j = 0; j < 3; j++) { ys[j] += e * ssin[a][j]; xc[j] += e * scos[a][j]; }
        }
#pragma unroll
        for (int j = 0; j < 3; j++) g_ang[t][b][j] = atan2f(ys[j], xc[j]);
    }
}

// ---------------- NeRF coordinate extension ----------------
__global__ void coord_scan_kernel(float* __restrict__ out)
{
    const int b = threadIdx.x;
    const float rl[3] = {1.458f, 1.525f, 1.33f};
    const float th[3] = {2.124f, 1.941f, 2.028f};
    float rct[3], rst[3];
#pragma unroll
    for (int j = 0; j < 3; j++) { rct[j] = rl[j] * cosf(th[j]); rst[j] = rl[j] * sinf(th[j]); }

    float ax = 0.f, ay = 0.f, az = 0.f;
    float bx = 1.458f, by = 0.f, bz = 0.f;
    float cx = 2.f, cy = 1.f, cz = 0.f;

    for (int n = 0; n < 3 * T; n++) {
        int tt = n / 3, j = n - 3 * tt;
        float phi = g_ang[tt][b][j];
        float bcx = cx - bx, bcy = cy - by, bcz = cz - bz;
        float inv = rsqrtf(bcx * bcx + bcy * bcy + bcz * bcz);
        bcx *= inv; bcy *= inv; bcz *= inv;
        float abx = bx - ax, aby = by - ay, abz = bz - az;
        float nx = aby * bcz - abz * bcy;
        float ny = abz * bcx - abx * bcz;
        float nz = abx * bcy - aby * bcx;
        inv = rsqrtf(nx * nx + ny * ny + nz * nz);
        nx *= inv; ny *= inv; nz *= inv;
        float mx = ny * bcz - nz * bcy;
        float my = nz * bcx - nx * bcz;
        float mz = nx * bcy - ny * bcx;
        float sphi, cphi;
        __sincosf(phi, &sphi, &cphi);
        float dx = cx - rct[j] * bcx + rst[j] * (cphi * mx + sphi * nx);
        float dy = cy - rct[j] * bcy + rst[j] * (cphi * my + sphi * ny);
        float dz = cz - rct[j] * bcz + rst[j] * (cphi * mz + sphi * nz);
        float* o = out + (n * B + b) * 3;
        o[0] = dx; o[1] = dy; o[2] = dz;
        ax = bx; ay = by; az = bz;
        bx = cx; by = cy; bz = cz;
        cx = dx; cy = dy; cz = dz;
    }
}

// ---------------- launch (8 graph nodes) ----------------
extern "C" void kernel_launch(void* const* d_in, const int* in_sizes, int n_in,
                              void* d_out, int out_size)
{
    const float* x      = (const float*)d_in[0];
    const float* Wih_f0 = (const float*)d_in[1];
    const float* Whh_f0 = (const float*)d_in[2];
    const float* b_f0   = (const float*)d_in[3];
    const float* Wih_b0 = (const float*)d_in[4];
    const float* Whh_b0 = (const float*)d_in[5];
    const float* b_b0   = (const float*)d_in[6];
    const float* Wih_f1 = (const float*)d_in[7];
    const float* Whh_f1 = (const float*)d_in[8];
    const float* b_f1   = (const float*)d_in[9];
    const float* Wih_b1 = (const float*)d_in[10];
    const float* Whh_b1 = (const float*)d_in[11];
    const float* b_b1   = (const float*)d_in[12];
    const float* Wl     = (const float*)d_in[13];
    const float* bl     = (const float*)d_in[14];
    const float* alpha  = (const float*)d_in[15];
    float* out = (float*)d_out;

    const int smem_rec = (SWF + SWXF + SXF + 2 * BUFF) * (int)sizeof(float); // 222,464 B
    const int smem_xs1 = 2 * 10496 * (int)sizeof(float);                     // 83,968 B
    cudaFuncSetAttribute(lstm_persist<0>, cudaFuncAttributeMaxDynamicSharedMemorySize, smem_rec);
    cudaFuncSetAttribute(lstm_persist<1>, cudaFuncAttributeMaxDynamicSharedMemorySize, smem_rec);
    cudaFuncSetAttribute(xs1_gemm, cudaFuncAttributeMaxDynamicSharedMemorySize, smem_xs1);

    prep_wp<<<1300, 256>>>(Wih_f0, Wih_b0);
    zero_kernel<<<400, 256>>>();
    lstm_persist<0><<<NBLK, 384, smem_rec>>>(x, Whh_f0, b_f0, Whh_b0, b_b0);
    xs1_gemm<<<dim3(25, 256, 2), 128, smem_xs1>>>(Wih_f1, Wih_b1);
    zero_state_only<<<400, 256>>>();
    lstm_persist<1><<<NBLK, 384, smem_rec>>>(nullptr, Whh_f1, b_f1, Whh_b1, b_b1);
    logits_angles<<<T, 640>>>(Wl, bl, alpha);
    coord_scan_kernel<<<1, 32>>>(out);
}